// round 1
// baseline (speedup 1.0000x reference)
#include <cuda_runtime.h>

// FraudDetectionModel: out[r] = Wf . h4(x[r]) + bf,
// h_{l+1} = tanh(h_l @ W_l^T + b_l) * s_l + t_l, 4 layers, dims 2->2.
// MUFU-bound baseline: tanh.approx.f32 (1 MUFU.TANH per activation).

#define BATCH 16777216
#define ROWS_PER_THREAD 2
#define THREADS 256

__device__ __forceinline__ float fast_tanh(float x) {
    float y;
    asm("tanh.approx.f32 %0, %1;" : "=f"(y) : "f"(x));
    return y;
}

__global__ void __launch_bounds__(THREADS)
fraud_mlp_kernel(const float4* __restrict__ x,      // [B/2] pairs of rows
                 const float*  __restrict__ Ws,     // [4,2,2]
                 const float*  __restrict__ bs,     // [4,2]
                 const float*  __restrict__ sc,     // [4,2]
                 const float*  __restrict__ sh,     // [4,2]
                 const float*  __restrict__ Wf,     // [1,2]
                 const float*  __restrict__ bf,     // [1]
                 float2*       __restrict__ out,    // [B/2]
                 int n4)
{
    int i = blockIdx.x * blockDim.x + threadIdx.x;
    if (i >= n4) return;

    // --- load params into registers (uniform-address broadcast loads) ---
    float w[16], b[8], s[8], t[8];
#pragma unroll
    for (int k = 0; k < 16; k++) w[k] = __ldg(Ws + k);
#pragma unroll
    for (int k = 0; k < 8; k++)  b[k] = __ldg(bs + k);
#pragma unroll
    for (int k = 0; k < 8; k++)  s[k] = __ldg(sc + k);
#pragma unroll
    for (int k = 0; k < 8; k++)  t[k] = __ldg(sh + k);
    const float wf0 = __ldg(Wf + 0);
    const float wf1 = __ldg(Wf + 1);
    const float bff = __ldg(bf);

    const float4 xv = x[i];   // two rows: (x.x,x.y) and (x.z,x.w)

    // row A
    float a0 = xv.x, a1 = xv.y;
    // row B
    float c0 = xv.z, c1 = xv.w;

#pragma unroll
    for (int l = 0; l < 4; l++) {
        const float w00 = w[l*4+0], w01 = w[l*4+1];
        const float w10 = w[l*4+2], w11 = w[l*4+3];
        const float b0  = b[l*2+0], b1  = b[l*2+1];
        const float s0  = s[l*2+0], s1  = s[l*2+1];
        const float t0  = t[l*2+0], t1  = t[l*2+1];

        float ua0 = fmaf(w00, a0, fmaf(w01, a1, b0));
        float ua1 = fmaf(w10, a0, fmaf(w11, a1, b1));
        float uc0 = fmaf(w00, c0, fmaf(w01, c1, b0));
        float uc1 = fmaf(w10, c0, fmaf(w11, c1, b1));

        // 4 independent MUFU.TANH back-to-back: good MLP on the XU pipe
        float ta0 = fast_tanh(ua0);
        float ta1 = fast_tanh(ua1);
        float tc0 = fast_tanh(uc0);
        float tc1 = fast_tanh(uc1);

        a0 = fmaf(ta0, s0, t0);
        a1 = fmaf(ta1, s1, t1);
        c0 = fmaf(tc0, s0, t0);
        c1 = fmaf(tc1, s1, t1);
    }

    float oa = fmaf(wf0, a0, fmaf(wf1, a1, bff));
    float ob = fmaf(wf0, c0, fmaf(wf1, c1, bff));

    out[i] = make_float2(oa, ob);
}

extern "C" void kernel_launch(void* const* d_in, const int* in_sizes, int n_in,
                              void* d_out, int out_size)
{
    const float4* x  = (const float4*)d_in[0];
    const float*  Ws = (const float*)d_in[1];
    const float*  bs = (const float*)d_in[2];
    const float*  sc = (const float*)d_in[3];
    const float*  sh = (const float*)d_in[4];
    const float*  Wf = (const float*)d_in[5];
    const float*  bf = (const float*)d_in[6];
    float2* out = (float2*)d_out;

    const int n4 = BATCH / 2;                  // 8,388,608 thread work-items
    const int blocks = n4 / THREADS;           // 32768 blocks, exact
    fraud_mlp_kernel<<<blocks, THREADS>>>(x, Ws, bs, sc, sh, Wf, bf, out, n4);
}

// round 2
// speedup vs baseline: 1.4155x; 1.4155x over previous
#include <cuda_runtime.h>

// FraudDetectionModel: out[r] = Wf . h4(x[r]) + bf,
// h_{l+1} = tanh(h_l @ W_l^T + b_l) * s_l + t_l, 4 layers, dims 2->2.
// R2: params in __constant__ (kills 40 LDG/thread that saturated L1tex),
//     4 rows per thread (2x float4 in, 1x float4 out).

#define BATCH 16777216
#define THREADS 256
#define ROWS_PER_THREAD 4

// Packed constant parameter block:
// [0:16)  Ws (4 layers x 2x2, row-major W[l][out][in])
// [16:24) bs
// [24:32) scales
// [32:40) shifts
// [40:42) Wf
// [42]    bf
__constant__ float c_params[43];

__device__ __forceinline__ float fast_tanh(float x) {
    float y;
    asm("tanh.approx.f32 %0, %1;" : "=f"(y) : "f"(x));
    return y;
}

__global__ void __launch_bounds__(THREADS)
fraud_mlp_kernel(const float4* __restrict__ x,   // [B/2] row pairs
                 float4*       __restrict__ out) // [B/4] quad outputs
{
    const int i = blockIdx.x * blockDim.x + threadIdx.x;

    const float4 xv0 = x[2 * i + 0];  // rows 0,1
    const float4 xv1 = x[2 * i + 1];  // rows 2,3

    float h0a = xv0.x, h0b = xv0.y;   // row 0 state
    float h1a = xv0.z, h1b = xv0.w;   // row 1
    float h2a = xv1.x, h2b = xv1.y;   // row 2
    float h3a = xv1.z, h3b = xv1.w;   // row 3

#pragma unroll
    for (int l = 0; l < 4; l++) {
        const float w00 = c_params[l * 4 + 0];
        const float w01 = c_params[l * 4 + 1];
        const float w10 = c_params[l * 4 + 2];
        const float w11 = c_params[l * 4 + 3];
        const float b0  = c_params[16 + l * 2 + 0];
        const float b1  = c_params[16 + l * 2 + 1];
        const float s0  = c_params[24 + l * 2 + 0];
        const float s1  = c_params[24 + l * 2 + 1];
        const float t0  = c_params[32 + l * 2 + 0];
        const float t1  = c_params[32 + l * 2 + 1];

        float u0a = fmaf(w00, h0a, fmaf(w01, h0b, b0));
        float u0b = fmaf(w10, h0a, fmaf(w11, h0b, b1));
        float u1a = fmaf(w00, h1a, fmaf(w01, h1b, b0));
        float u1b = fmaf(w10, h1a, fmaf(w11, h1b, b1));
        float u2a = fmaf(w00, h2a, fmaf(w01, h2b, b0));
        float u2b = fmaf(w10, h2a, fmaf(w11, h2b, b1));
        float u3a = fmaf(w00, h3a, fmaf(w01, h3b, b0));
        float u3b = fmaf(w10, h3a, fmaf(w11, h3b, b1));

        float v0a = fast_tanh(u0a);
        float v0b = fast_tanh(u0b);
        float v1a = fast_tanh(u1a);
        float v1b = fast_tanh(u1b);
        float v2a = fast_tanh(u2a);
        float v2b = fast_tanh(u2b);
        float v3a = fast_tanh(u3a);
        float v3b = fast_tanh(u3b);

        h0a = fmaf(v0a, s0, t0);  h0b = fmaf(v0b, s1, t1);
        h1a = fmaf(v1a, s0, t0);  h1b = fmaf(v1b, s1, t1);
        h2a = fmaf(v2a, s0, t0);  h2b = fmaf(v2b, s1, t1);
        h3a = fmaf(v3a, s0, t0);  h3b = fmaf(v3b, s1, t1);
    }

    const float wf0 = c_params[40];
    const float wf1 = c_params[41];
    const float bff = c_params[42];

    float4 o;
    o.x = fmaf(wf0, h0a, fmaf(wf1, h0b, bff));
    o.y = fmaf(wf0, h1a, fmaf(wf1, h1b, bff));
    o.z = fmaf(wf0, h2a, fmaf(wf1, h2b, bff));
    o.w = fmaf(wf0, h3a, fmaf(wf1, h3b, bff));

    out[i] = o;
}

extern "C" void kernel_launch(void* const* d_in, const int* in_sizes, int n_in,
                              void* d_out, int out_size)
{
    const float4* x = (const float4*)d_in[0];
    float4* out = (float4*)d_out;

    // Stage all 43 scalars into the constant bank (D2D, graph-capturable).
    cudaMemcpyToSymbolAsync(c_params, d_in[1], 16 * sizeof(float),
                            0 * sizeof(float), cudaMemcpyDeviceToDevice, 0);
    cudaMemcpyToSymbolAsync(c_params, d_in[2], 8 * sizeof(float),
                            16 * sizeof(float), cudaMemcpyDeviceToDevice, 0);
    cudaMemcpyToSymbolAsync(c_params, d_in[3], 8 * sizeof(float),
                            24 * sizeof(float), cudaMemcpyDeviceToDevice, 0);
    cudaMemcpyToSymbolAsync(c_params, d_in[4], 8 * sizeof(float),
                            32 * sizeof(float), cudaMemcpyDeviceToDevice, 0);
    cudaMemcpyToSymbolAsync(c_params, d_in[5], 2 * sizeof(float),
                            40 * sizeof(float), cudaMemcpyDeviceToDevice, 0);
    cudaMemcpyToSymbolAsync(c_params, d_in[6], 1 * sizeof(float),
                            42 * sizeof(float), cudaMemcpyDeviceToDevice, 0);

    const int nthreads = BATCH / ROWS_PER_THREAD;   // 4,194,304
    const int blocks = nthreads / THREADS;          // 16384
    fraud_mlp_kernel<<<blocks, THREADS>>>(x, out);
}

// round 3
// speedup vs baseline: 1.6468x; 1.1634x over previous
#include <cuda_runtime.h>

// FraudDetectionModel R3:
//  - prep kernel folds scale/shift/bias into adjacent layer weights
//    (26 FMA + 8 tanh -> 18 FMA + 8 tanh per row) and packs them, so the
//    graph needs just ONE memcpyToSymbol node instead of six.
//  - main kernel: 8 rows/thread, 4x LDG.128 front-batched, streaming
//    cache hints (.cs) for pure streaming traffic.

#define BATCH 16777216
#define THREADS 256
#define ROWS_PER_THREAD 8

// Folded constant block:
// [0:4)   W0            [4:6)   b0
// [6:10)  W'1           [10:12) b'1
// [12:16) W'2           [16:18) b'2
// [18:22) W'3           [22:24) b'3
// [24:26) wf'           [26]    bf'
__constant__ float c_fold[28];
__device__ float g_fold[28];

__device__ __forceinline__ float fast_tanh(float x) {
    float y;
    asm("tanh.approx.f32 %0, %1;" : "=f"(y) : "f"(x));
    return y;
}

__device__ __forceinline__ float4 ldcs4(const float4* p) {
    float4 v;
    asm volatile("ld.global.cs.v4.f32 {%0,%1,%2,%3}, [%4];"
                 : "=f"(v.x), "=f"(v.y), "=f"(v.z), "=f"(v.w) : "l"(p));
    return v;
}
__device__ __forceinline__ void stcs4(float4* p, float4 v) {
    asm volatile("st.global.cs.v4.f32 [%0], {%1,%2,%3,%4};"
                 :: "l"(p), "f"(v.x), "f"(v.y), "f"(v.z), "f"(v.w));
}

__global__ void fold_params_kernel(const float* __restrict__ Ws,   // [4,2,2]
                                   const float* __restrict__ bs,   // [4,2]
                                   const float* __restrict__ sc,   // [4,2]
                                   const float* __restrict__ sh,   // [4,2]
                                   const float* __restrict__ Wf,   // [1,2]
                                   const float* __restrict__ bf)   // [1]
{
    if (threadIdx.x != 0) return;

    // layer 0: unchanged
    g_fold[0] = Ws[0]; g_fold[1] = Ws[1]; g_fold[2] = Ws[2]; g_fold[3] = Ws[3];
    g_fold[4] = bs[0]; g_fold[5] = bs[1];

    // layers 1..3: W'_l = W_l * diag(s_{l-1}); b'_l = W_l t_{l-1} + b_l
#pragma unroll
    for (int l = 1; l < 4; l++) {
        const float w00 = Ws[l*4+0], w01 = Ws[l*4+1];
        const float w10 = Ws[l*4+2], w11 = Ws[l*4+3];
        const float sp0 = sc[(l-1)*2+0], sp1 = sc[(l-1)*2+1];
        const float tp0 = sh[(l-1)*2+0], tp1 = sh[(l-1)*2+1];
        const int base = 6 + (l-1)*6;
        g_fold[base+0] = w00 * sp0;
        g_fold[base+1] = w01 * sp1;
        g_fold[base+2] = w10 * sp0;
        g_fold[base+3] = w11 * sp1;
        g_fold[base+4] = fmaf(w00, tp0, fmaf(w01, tp1, bs[l*2+0]));
        g_fold[base+5] = fmaf(w10, tp0, fmaf(w11, tp1, bs[l*2+1]));
    }

    // final: wf' = Wf * diag(s_3); bf' = Wf t_3 + bf
    const float s30 = sc[6], s31 = sc[7];
    const float t30 = sh[6], t31 = sh[7];
    g_fold[24] = Wf[0] * s30;
    g_fold[25] = Wf[1] * s31;
    g_fold[26] = fmaf(Wf[0], t30, fmaf(Wf[1], t31, bf[0]));
    g_fold[27] = 0.0f;
}

__global__ void __launch_bounds__(THREADS)
fraud_mlp_kernel(const float4* __restrict__ x,   // [B/2] row pairs
                 float4*       __restrict__ out) // [B/4] quad outputs
{
    const int i = blockIdx.x * blockDim.x + threadIdx.x;

    // 8 rows: 4 front-batched 128-bit streaming loads
    float4 xv[4];
#pragma unroll
    for (int k = 0; k < 4; k++) xv[k] = ldcs4(x + 4 * i + k);

    float ha[8], hb[8];
#pragma unroll
    for (int k = 0; k < 4; k++) {
        ha[2*k+0] = xv[k].x; hb[2*k+0] = xv[k].y;
        ha[2*k+1] = xv[k].z; hb[2*k+1] = xv[k].w;
    }

    // layer 0 (raw W0, b0), then folded layers 1..3: h <- tanh(W h + b)
#pragma unroll
    for (int l = 0; l < 4; l++) {
        const float w00 = c_fold[l*6+0], w01 = c_fold[l*6+1];
        const float w10 = c_fold[l*6+2], w11 = c_fold[l*6+3];
        const float b0  = c_fold[l*6+4], b1  = c_fold[l*6+5];
#pragma unroll
        for (int r = 0; r < 8; r++) {
            float u0 = fmaf(w00, ha[r], fmaf(w01, hb[r], b0));
            float u1 = fmaf(w10, ha[r], fmaf(w11, hb[r], b1));
            ha[r] = fast_tanh(u0);
            hb[r] = fast_tanh(u1);
        }
    }

    const float wf0 = c_fold[24], wf1 = c_fold[25], bff = c_fold[26];

    float o[8];
#pragma unroll
    for (int r = 0; r < 8; r++)
        o[r] = fmaf(wf0, ha[r], fmaf(wf1, hb[r], bff));

    float4 o0 = make_float4(o[0], o[1], o[2], o[3]);
    float4 o1 = make_float4(o[4], o[5], o[6], o[7]);
    stcs4(out + 2 * i + 0, o0);
    stcs4(out + 2 * i + 1, o1);
}

extern "C" void kernel_launch(void* const* d_in, const int* in_sizes, int n_in,
                              void* d_out, int out_size)
{
    const float4* x = (const float4*)d_in[0];
    float4* out = (float4*)d_out;

    fold_params_kernel<<<1, 32>>>((const float*)d_in[1], (const float*)d_in[2],
                                  (const float*)d_in[3], (const float*)d_in[4],
                                  (const float*)d_in[5], (const float*)d_in[6]);

    void* g_fold_addr = nullptr;
    cudaGetSymbolAddress(&g_fold_addr, g_fold);
    cudaMemcpyToSymbolAsync(c_fold, g_fold_addr, 28 * sizeof(float),
                            0, cudaMemcpyDeviceToDevice, 0);

    const int nthreads = BATCH / ROWS_PER_THREAD;   // 2,097,152
    const int blocks = nthreads / THREADS;          // 8192
    fraud_mlp_kernel<<<blocks, THREADS>>>(x, out);
}

// round 4
// speedup vs baseline: 1.7124x; 1.0398x over previous
#include <cuda_runtime.h>

// FraudDetectionModel R4: single-kernel, single graph node.
//  - Param fold (scale/shift/bias folded into adjacent weights) computed
//    per-block by thread 0 into shared memory (43 broadcast LDGs, cheap),
//    overlapped with the data LDG.128s issued before the barrier.
//  - 4 rows/thread (R2's best memory config), plain cached ld/st
//    (.cs hints regressed L1/DRAM in R3 — reverted).

#define BATCH 16777216
#define THREADS 256
#define ROWS_PER_THREAD 4

__device__ __forceinline__ float fast_tanh(float x) {
    float y;
    asm("tanh.approx.f32 %0, %1;" : "=f"(y) : "f"(x));
    return y;
}

// Shared folded parameter block:
// [l*6 + 0..3] W'_l (2x2)   [l*6 + 4..5] b'_l     for l = 0..3
// [24:26) wf'   [26] bf'
__global__ void __launch_bounds__(THREADS)
fraud_mlp_kernel(const float4* __restrict__ x,    // [B/2] row pairs
                 float4*       __restrict__ out,  // [B/4] quad outputs
                 const float*  __restrict__ Ws,   // [4,2,2]
                 const float*  __restrict__ bs,   // [4,2]
                 const float*  __restrict__ sc,   // [4,2]
                 const float*  __restrict__ sh,   // [4,2]
                 const float*  __restrict__ Wf,   // [1,2]
                 const float*  __restrict__ bf)   // [1]
{
    __shared__ float p[28];

    const int i = blockIdx.x * blockDim.x + threadIdx.x;

    // Issue data loads BEFORE the barrier: fold overlaps LDG latency.
    const float4 xv0 = x[2 * i + 0];   // rows 0,1
    const float4 xv1 = x[2 * i + 1];   // rows 2,3

    if (threadIdx.x == 0) {
        // layer 0 unchanged
        p[0] = __ldg(Ws + 0); p[1] = __ldg(Ws + 1);
        p[2] = __ldg(Ws + 2); p[3] = __ldg(Ws + 3);
        p[4] = __ldg(bs + 0); p[5] = __ldg(bs + 1);

        // layers 1..3: W'_l = W_l * diag(s_{l-1}); b'_l = W_l t_{l-1} + b_l
#pragma unroll
        for (int l = 1; l < 4; l++) {
            const float w00 = __ldg(Ws + l * 4 + 0), w01 = __ldg(Ws + l * 4 + 1);
            const float w10 = __ldg(Ws + l * 4 + 2), w11 = __ldg(Ws + l * 4 + 3);
            const float sp0 = __ldg(sc + (l - 1) * 2 + 0), sp1 = __ldg(sc + (l - 1) * 2 + 1);
            const float tp0 = __ldg(sh + (l - 1) * 2 + 0), tp1 = __ldg(sh + (l - 1) * 2 + 1);
            p[l * 6 + 0] = w00 * sp0;
            p[l * 6 + 1] = w01 * sp1;
            p[l * 6 + 2] = w10 * sp0;
            p[l * 6 + 3] = w11 * sp1;
            p[l * 6 + 4] = fmaf(w00, tp0, fmaf(w01, tp1, __ldg(bs + l * 2 + 0)));
            p[l * 6 + 5] = fmaf(w10, tp0, fmaf(w11, tp1, __ldg(bs + l * 2 + 1)));
        }

        // final: wf' = Wf * diag(s_3); bf' = Wf t_3 + bf
        const float s30 = __ldg(sc + 6), s31 = __ldg(sc + 7);
        const float t30 = __ldg(sh + 6), t31 = __ldg(sh + 7);
        const float f0 = __ldg(Wf + 0), f1 = __ldg(Wf + 1);
        p[24] = f0 * s30;
        p[25] = f1 * s31;
        p[26] = fmaf(f0, t30, fmaf(f1, t31, __ldg(bf)));
        p[27] = 0.0f;
    }
    __syncthreads();

    float ha[4], hb[4];
    ha[0] = xv0.x; hb[0] = xv0.y;
    ha[1] = xv0.z; hb[1] = xv0.w;
    ha[2] = xv1.x; hb[2] = xv1.y;
    ha[3] = xv1.z; hb[3] = xv1.w;

#pragma unroll
    for (int l = 0; l < 4; l++) {
        const float w00 = p[l * 6 + 0], w01 = p[l * 6 + 1];
        const float w10 = p[l * 6 + 2], w11 = p[l * 6 + 3];
        const float b0  = p[l * 6 + 4], b1  = p[l * 6 + 5];
#pragma unroll
        for (int r = 0; r < 4; r++) {
            float u0 = fmaf(w00, ha[r], fmaf(w01, hb[r], b0));
            float u1 = fmaf(w10, ha[r], fmaf(w11, hb[r], b1));
            ha[r] = fast_tanh(u0);
            hb[r] = fast_tanh(u1);
        }
    }

    const float wf0 = p[24], wf1 = p[25], bff = p[26];

    float4 o;
    o.x = fmaf(wf0, ha[0], fmaf(wf1, hb[0], bff));
    o.y = fmaf(wf0, ha[1], fmaf(wf1, hb[1], bff));
    o.z = fmaf(wf0, ha[2], fmaf(wf1, hb[2], bff));
    o.w = fmaf(wf0, ha[3], fmaf(wf1, hb[3], bff));

    out[i] = o;
}

extern "C" void kernel_launch(void* const* d_in, const int* in_sizes, int n_in,
                              void* d_out, int out_size)
{
    const float4* x = (const float4*)d_in[0];
    float4* out = (float4*)d_out;

    const int nthreads = BATCH / ROWS_PER_THREAD;   // 4,194,304
    const int blocks = nthreads / THREADS;          // 16384
    fraud_mlp_kernel<<<blocks, THREADS>>>(
        x, out,
        (const float*)d_in[1], (const float*)d_in[2], (const float*)d_in[3],
        (const float*)d_in[4], (const float*)d_in[5], (const float*)d_in[6]);
}

// round 5
// speedup vs baseline: 1.7543x; 1.0245x over previous
#include <cuda_runtime.h>

// FraudDetectionModel R5: single graph node.
//  - Param fold computed by thread 0 into shared (overlapped with data LDGs).
//  - All threads read params via 7x LDS.128 (was 28 scalar LDS in R4, which
//    pushed L1tex to 53% and cost 2.5us) into registers.
//  - 4 rows/thread, plain cached ld/st.

#define BATCH 16777216
#define THREADS 256
#define ROWS_PER_THREAD 4

__device__ __forceinline__ float fast_tanh(float x) {
    float y;
    asm("tanh.approx.f32 %0, %1;" : "=f"(y) : "f"(x));
    return y;
}

// Folded parameter block (28 floats, 16B-aligned for float4 LDS):
// [l*6 + 0..3] W'_l (2x2)   [l*6 + 4..5] b'_l   for l = 0..3
// [24:26) wf'   [26] bf'   [27] pad
__global__ void __launch_bounds__(THREADS)
fraud_mlp_kernel(const float4* __restrict__ x,    // [B/2] row pairs
                 float4*       __restrict__ out,  // [B/4] quad outputs
                 const float*  __restrict__ Ws,   // [4,2,2]
                 const float*  __restrict__ bs,   // [4,2]
                 const float*  __restrict__ sc,   // [4,2]
                 const float*  __restrict__ sh,   // [4,2]
                 const float*  __restrict__ Wf,   // [1,2]
                 const float*  __restrict__ bf)   // [1]
{
    __shared__ __align__(16) float p[28];

    const int i = blockIdx.x * blockDim.x + threadIdx.x;

    // Data loads issued BEFORE the barrier: fold overlaps LDG latency.
    const float4 xv0 = x[2 * i + 0];   // rows 0,1
    const float4 xv1 = x[2 * i + 1];   // rows 2,3

    if (threadIdx.x == 0) {
        // layer 0 unchanged
        p[0] = __ldg(Ws + 0); p[1] = __ldg(Ws + 1);
        p[2] = __ldg(Ws + 2); p[3] = __ldg(Ws + 3);
        p[4] = __ldg(bs + 0); p[5] = __ldg(bs + 1);

        // layers 1..3: W'_l = W_l * diag(s_{l-1}); b'_l = W_l t_{l-1} + b_l
#pragma unroll
        for (int l = 1; l < 4; l++) {
            const float w00 = __ldg(Ws + l * 4 + 0), w01 = __ldg(Ws + l * 4 + 1);
            const float w10 = __ldg(Ws + l * 4 + 2), w11 = __ldg(Ws + l * 4 + 3);
            const float sp0 = __ldg(sc + (l - 1) * 2 + 0), sp1 = __ldg(sc + (l - 1) * 2 + 1);
            const float tp0 = __ldg(sh + (l - 1) * 2 + 0), tp1 = __ldg(sh + (l - 1) * 2 + 1);
            p[l * 6 + 0] = w00 * sp0;
            p[l * 6 + 1] = w01 * sp1;
            p[l * 6 + 2] = w10 * sp0;
            p[l * 6 + 3] = w11 * sp1;
            p[l * 6 + 4] = fmaf(w00, tp0, fmaf(w01, tp1, __ldg(bs + l * 2 + 0)));
            p[l * 6 + 5] = fmaf(w10, tp0, fmaf(w11, tp1, __ldg(bs + l * 2 + 1)));
        }

        // final: wf' = Wf * diag(s_3); bf' = Wf t_3 + bf
        const float s30 = __ldg(sc + 6), s31 = __ldg(sc + 7);
        const float t30 = __ldg(sh + 6), t31 = __ldg(sh + 7);
        const float f0 = __ldg(Wf + 0), f1 = __ldg(Wf + 1);
        p[24] = f0 * s30;
        p[25] = f1 * s31;
        p[26] = fmaf(f0, t30, fmaf(f1, t31, __ldg(bf)));
        p[27] = 0.0f;
    }
    __syncthreads();

    // Pull all params into registers via 7 vectorized LDS.128 (broadcast).
    float pr[28];
    const float4* pv = reinterpret_cast<const float4*>(p);
#pragma unroll
    for (int k = 0; k < 7; k++) {
        float4 v = pv[k];
        pr[4 * k + 0] = v.x;
        pr[4 * k + 1] = v.y;
        pr[4 * k + 2] = v.z;
        pr[4 * k + 3] = v.w;
    }

    float ha[4], hb[4];
    ha[0] = xv0.x; hb[0] = xv0.y;
    ha[1] = xv0.z; hb[1] = xv0.w;
    ha[2] = xv1.x; hb[2] = xv1.y;
    ha[3] = xv1.z; hb[3] = xv1.w;

#pragma unroll
    for (int l = 0; l < 4; l++) {
        const float w00 = pr[l * 6 + 0], w01 = pr[l * 6 + 1];
        const float w10 = pr[l * 6 + 2], w11 = pr[l * 6 + 3];
        const float b0  = pr[l * 6 + 4], b1  = pr[l * 6 + 5];
#pragma unroll
        for (int r = 0; r < 4; r++) {
            float u0 = fmaf(w00, ha[r], fmaf(w01, hb[r], b0));
            float u1 = fmaf(w10, ha[r], fmaf(w11, hb[r], b1));
            ha[r] = fast_tanh(u0);
            hb[r] = fast_tanh(u1);
        }
    }

    const float wf0 = pr[24], wf1 = pr[25], bff = pr[26];

    float4 o;
    o.x = fmaf(wf0, ha[0], fmaf(wf1, hb[0], bff));
    o.y = fmaf(wf0, ha[1], fmaf(wf1, hb[1], bff));
    o.z = fmaf(wf0, ha[2], fmaf(wf1, hb[2], bff));
    o.w = fmaf(wf0, ha[3], fmaf(wf1, hb[3], bff));

    out[i] = o;
}

extern "C" void kernel_launch(void* const* d_in, const int* in_sizes, int n_in,
                              void* d_out, int out_size)
{
    const float4* x = (const float4*)d_in[0];
    float4* out = (float4*)d_out;

    const int nthreads = BATCH / ROWS_PER_THREAD;   // 4,194,304
    const int blocks = nthreads / THREADS;          // 16384
    fraud_mlp_kernel<<<blocks, THREADS>>>(
        x, out,
        (const float*)d_in[1], (const float*)d_in[2], (const float*)d_in[3],
        (const float*)d_in[4], (const float*)d_in[5], (const float*)d_in[6]);
}